// round 15
// baseline (speedup 1.0000x reference)
#include <cuda_runtime.h>
#include <cuda_fp16.h>
#include <math.h>
#include <stdint.h>

#define NB 256
#define NI 512   // outputs (i)
#define NJ 512   // inputs  (j) -> contraction K
#define NW 64

// Scratch (static device arrays: allocation rules OK)
// j-index is stored PERMUTED within each 16-block (see permj) so gemm fragment
// loads become single LDS.64s.
__device__ __half g_inT  [(size_t)NW * NB * NJ];   // [w][b][pj]  16.8 MB fp16
__device__ __half g_dropT[(size_t)NW * NI * NJ];   // [w][i][pj]  33.5 MB fp16
__device__ float  g_outT [(size_t)NW * NB * NI];   // [w][b][i]   33.5 MB f32

// permute j within its 16-block: [0,1,8,9, 2,3,10,11, 4,5,12,13, 6,7,14,15]
// pos = (j&~15) | ((j>>1)&3)<<2 | ((j>>3)&1)<<1 | (j&1)   (pairs stay adjacent)
__device__ __forceinline__ int permj(int j) {
    return (j & ~15) | (((j >> 1) & 3) << 2) | (((j >> 3) & 1) << 1) | (j & 1);
}

// ---------------------------------------------------------------------------
// Kernel 1: transpose input [b][j][w] -> inT[w][b][permj(j)], fp16.
// ---------------------------------------------------------------------------
__global__ void __launch_bounds__(256) tin_kernel(const float* __restrict__ in) {
    __shared__ float s[32][65];
    const int b  = blockIdx.y;
    const int j0 = blockIdx.x * 32;     // multiple of 32 -> permj applies within
    const int t  = threadIdx.x;

    {   // load 32 j-rows x 64 w (256B per row)
        int r = t >> 3, wq = (t & 7) * 8;
        const float4* src = (const float4*)(in + ((size_t)b * NJ + j0 + r) * NW + wq);
        float4 v0 = src[0], v1 = src[1];
        s[r][wq + 0] = v0.x; s[r][wq + 1] = v0.y; s[r][wq + 2] = v0.z; s[r][wq + 3] = v0.w;
        s[r][wq + 4] = v1.x; s[r][wq + 5] = v1.y; s[r][wq + 6] = v1.z; s[r][wq + 7] = v1.w;
    }
    __syncthreads();
    {   // write 64 w-rows x 32 j as fp16, permuted (4B pair stores)
        int w = t >> 2, jg = (t & 3) * 8;
        __half* dst = g_inT + ((size_t)w * NB + b) * NJ + j0;
#pragma unroll
        for (int u = 0; u < 4; u++) {
            __half2 h = __floats2half2_rn(s[jg + 2 * u][w], s[jg + 2 * u + 1][w]);
            *(__half2*)&dst[permj(jg + 2 * u)] = h;
        }
    }
}

// ---------------------------------------------------------------------------
// Kernel 2: dropT[w][i][permj(j)], fp16, MUFU cos.
// denom2 = 1 - 2 at cos + at^2.  Kerr term (~2.7e-19 rad) below fp32 eps.
// __cosf: rel_err impact measured negligible (R6: 3.0029e-4 vs 3.0012e-4).
// ---------------------------------------------------------------------------
__global__ void __launch_bounds__(256) dropT_kernel(
        const float* __restrict__ phase_shift,
        const float* __restrict__ coupling) {
    const int j = blockIdx.x * 256 + threadIdx.x;
    const int i = blockIdx.y;
    const int k = i * NJ + j;

    const double WLMIN = 1.53e-06, WLMAX = 1.57e-06;
    double c    = WLMIN + (WLMAX - WLMIN) * ((double)k / (double)(NI * NJ));
    double pref = (4.0 * M_PI * M_PI * 4.2 * 5e-06) / (c * c);   // 2*pi/fsr
    const float base = (float)(pref * (WLMIN - c)) + phase_shift[k];
    const float dphi = (float)(pref * ((WLMAX - WLMIN) / 63.0));

    float kap = fminf(fmaxf(coupling[k], 0.1f), 0.9f);
    float t   = sqrtf(1.0f - kap * kap);
    const float alpha = (float)(1.0 - M_PI / 15000.0);
    float at  = alpha * t;
    const float A2    = 1.0f + at * at;
    const float twoAt = 2.0f * at;
    const float coef  = kap * kap * alpha;

    __half* dst = g_dropT + (size_t)i * NJ + permj(j);
#pragma unroll 8
    for (int w = 0; w < NW; w++) {
        float ph = fmaf((float)w, dphi, base);
        float d  = __fdividef(coef, A2 - twoAt * __cosf(ph));
        dst[(size_t)w * NI * NJ] = __float2half_rn(d);
    }
}

// ---------------------------------------------------------------------------
// Kernel 3: mma.sync fp16 m16n8k16 GEMM per w-plane.
// Same structure as R14 (passing, 80us) but with k-interleaved smem layout:
// every fragment load is one LDS.64 (12 LDS.64 + 16 MMA per ks vs 24 LDS.32).
// RSB=96: bank-slot 24g mod 32 = {0,24,16,8} -> each 16-lane phase covers all
// 32 banks, conflict-free for 8B loads.
// ---------------------------------------------------------------------------
#define TM 128
#define TN 128
#define KC 32                    // halves per chunk
#define NCH (NJ / KC)            // 16
#define RSB 96                   // smem row stride in bytes (64B data + 32B pad)
#define SBYT (128 * RSB)         // 12288 bytes per operand-stage
#define SMEM_REQ (4 * SBYT)      // 49152 bytes (2 stages x {A,B})

#define CPA(s, g) asm volatile("cp.async.ca.shared.global [%0], [%1], 16;" :: "r"(s), "l"(g))

#define MMA_F16(c, a0, a1, a2, a3, b0, b1) \
    asm volatile("mma.sync.aligned.m16n8k16.row.col.f32.f16.f16.f32 " \
        "{%0,%1,%2,%3}, {%4,%5,%6,%7}, {%8,%9}, {%0,%1,%2,%3};" \
        : "+f"((c)[0]), "+f"((c)[1]), "+f"((c)[2]), "+f"((c)[3]) \
        : "r"(a0), "r"(a1), "r"(a2), "r"(a3), "r"(b0), "r"(b1))

#define LDSD(r0_, r1_, addr) \
    asm volatile("ld.shared.v2.b32 {%0,%1}, [%2];" : "=r"(r0_), "=r"(r1_) : "r"(addr))

static __device__ __forceinline__ uint32_t smem_u32(const void* p) {
    uint32_t a;
    asm("{ .reg .u64 t; cvta.to.shared.u64 t, %1; cvt.u32.u64 %0, t; }" : "=r"(a) : "l"(p));
    return a;
}

__global__ void __launch_bounds__(256, 2) gemm_kernel() {
    extern __shared__ char smem[];           // [A0|A1|B0|B1], 12288B each
    const uint32_t sbase = smem_u32(smem);

    const int tid = threadIdx.x;
    const int w   = blockIdx.x;
    const int b0  = blockIdx.y * TM;
    const int i0  = blockIdx.z * TN;

    // loader: 512 16B-units per operand per stage; thread does rows r0 and r0+64
    const int r0 = tid >> 2, wc = tid & 3;
    const int r1 = r0 + 64;
    const __half* gA = g_inT   + ((size_t)w * NB + b0) * NJ;
    const __half* gB = g_dropT + ((size_t)w * NI + i0) * NJ;
    const uint32_t soA0 = (uint32_t)(r0 * RSB + wc * 16);
    const uint32_t soA1 = (uint32_t)(r1 * RSB + wc * 16);

#define STAGE(slot, jc) do { \
    CPA(sbase + (slot) * SBYT + soA0,       (const char*)(gA + (size_t)r0 * NJ + (jc)) + wc * 16); \
    CPA(sbase + (slot) * SBYT + soA1,       (const char*)(gA + (size_t)r1 * NJ + (jc)) + wc * 16); \
    CPA(sbase + (2 + (slot)) * SBYT + soA0, (const char*)(gB + (size_t)r0 * NJ + (jc)) + wc * 16); \
    CPA(sbase + (2 + (slot)) * SBYT + soA1, (const char*)(gB + (size_t)r1 * NJ + (jc)) + wc * 16); \
    asm volatile("cp.async.commit_group;" ::: "memory"); \
} while (0)

    // prologue: chunk 0 -> buf0, chunk 1 -> buf1
    STAGE(0, 0);
    STAGE(1, KC);

    const int lane = tid & 31, wid = tid >> 5;
    const int g = lane >> 2, q = lane & 3;
    const int wm = (wid >> 2) * 64;      // warp m-offset (0/64)
    const int wn = (wid & 3) * 32;       // warp n-offset (0..96)

    float acc[4][4][4];
#pragma unroll
    for (int mt = 0; mt < 4; mt++)
#pragma unroll
        for (int nt = 0; nt < 4; nt++)
#pragma unroll
            for (int r = 0; r < 4; r++) acc[mt][nt][r] = 0.0f;

    for (int ch = 0; ch < NCH; ch++) {
        if (ch < NCH - 1) asm volatile("cp.async.wait_group 1;" ::: "memory");
        else              asm volatile("cp.async.wait_group 0;" ::: "memory");
        __syncthreads();

        const int par = ch & 1;
        const uint32_t pA = sbase + par * SBYT;
        const uint32_t pB = sbase + (2 + par) * SBYT;

#pragma unroll
        for (int ks = 0; ks < 2; ks++) {          // 2 x k=16 per chunk
            const uint32_t k0 = (uint32_t)ks * 32 + (uint32_t)q * 8;  // bytes
            uint32_t a[4][4], b[4][2];
#pragma unroll
            for (int mt = 0; mt < 4; mt++) {
                const uint32_t ra = pA + (uint32_t)((wm + mt * 16 + g) * RSB) + k0;
                LDSD(a[mt][0], a[mt][2], ra);            // rows g:   k 2q,2q+1 | 2q+8,2q+9
                LDSD(a[mt][1], a[mt][3], ra + 8 * RSB);  // rows g+8: same k
            }
#pragma unroll
            for (int nt = 0; nt < 4; nt++) {
                const uint32_t rb = pB + (uint32_t)((wn + nt * 8 + g) * RSB) + k0;
                LDSD(b[nt][0], b[nt][1], rb);            // n g: k 2q,2q+1 | 2q+8,2q+9
            }
#pragma unroll
            for (int mt = 0; mt < 4; mt++)
#pragma unroll
                for (int nt = 0; nt < 4; nt++)
                    MMA_F16(acc[mt][nt], a[mt][0], a[mt][1], a[mt][2], a[mt][3],
                            b[nt][0], b[nt][1]);
        }

        if (ch + 2 < NCH) {
            __syncthreads();   // all warps done reading buf[par]
            STAGE(par, (size_t)(ch + 2) * KC);
        }
    }

    // ---- epilogue: coalesced float2 stores to g_outT[w][b][i] (proven) ----
#pragma unroll
    for (int mt = 0; mt < 4; mt++) {
        const int row = b0 + wm + mt * 16 + g;
#pragma unroll
        for (int nt = 0; nt < 4; nt++) {
            const int col = i0 + wn + nt * 8 + 2 * q;
            float2 v0 = make_float2(acc[mt][nt][0], acc[mt][nt][1]);
            float2 v1 = make_float2(acc[mt][nt][2], acc[mt][nt][3]);
            *(float2*)&g_outT[((size_t)w * NB + row)     * NI + col] = v0;
            *(float2*)&g_outT[((size_t)w * NB + row + 8) * NI + col] = v1;
        }
    }
}

// ---------------------------------------------------------------------------
// Kernel 4: transpose outT[w][b][i] -> out[b][i][w]
// ---------------------------------------------------------------------------
__global__ void __launch_bounds__(256) tout_kernel(float* __restrict__ out) {
    __shared__ float s[32][65];
    const int b  = blockIdx.y;
    const int i0 = blockIdx.x * 32;
    const int t  = threadIdx.x;

    {   // load 64 w-rows x 32 i
        int w = t >> 2, ig = (t & 3) * 8;
        const float4* src = (const float4*)(g_outT + ((size_t)w * NB + b) * NI + i0 + ig);
        float4 v0 = src[0], v1 = src[1];
        s[ig + 0][w] = v0.x; s[ig + 1][w] = v0.y; s[ig + 2][w] = v0.z; s[ig + 3][w] = v0.w;
        s[ig + 4][w] = v1.x; s[ig + 5][w] = v1.y; s[ig + 6][w] = v1.z; s[ig + 7][w] = v1.w;
    }
    __syncthreads();
    {   // write 32 i-rows x 64 w (256B per row)
        int r = t >> 3, wq = (t & 7) * 8;
        float* dst = out + ((size_t)b * NI + i0 + r) * NW + wq;
        float4 o0, o1;
        o0.x = s[r][wq + 0]; o0.y = s[r][wq + 1]; o0.z = s[r][wq + 2]; o0.w = s[r][wq + 3];
        o1.x = s[r][wq + 4]; o1.y = s[r][wq + 5]; o1.z = s[r][wq + 6]; o1.w = s[r][wq + 7];
        ((float4*)dst)[0] = o0; ((float4*)dst)[1] = o1;
    }
}

// ---------------------------------------------------------------------------
extern "C" void kernel_launch(void* const* d_in, const int* in_sizes, int n_in,
                              void* d_out, int out_size) {
    const float* input    = (const float*)d_in[0];  // [256,512,64]
    const float* phase    = (const float*)d_in[1];  // [512,512]
    const float* coupling = (const float*)d_in[2];  // [512,512]
    float* out            = (float*)d_out;          // [256,512,64]

    cudaFuncSetAttribute(gemm_kernel, cudaFuncAttributeMaxDynamicSharedMemorySize, SMEM_REQ);

    tin_kernel  <<<dim3(NJ / 32, NB), 256>>>(input);
    dropT_kernel<<<dim3(NJ / 256, NI), 256>>>(phase, coupling);
    gemm_kernel <<<dim3(NW, NB / TM, NI / TN), 256, SMEM_REQ>>>();
    tout_kernel <<<dim3(NI / 32, NB), 256>>>(out);
}

// round 16
// speedup vs baseline: 1.0837x; 1.0837x over previous
#include <cuda_runtime.h>
#include <cuda_fp16.h>
#include <math.h>
#include <stdint.h>

#define NB 256
#define NI 512   // outputs (i)
#define NJ 512   // inputs  (j) -> contraction K
#define NW 64

// Scratch (static device arrays: allocation rules OK)
// j-index stored PERMUTED within each 16-block (permj) -> LDS.64 fragment loads.
__device__ __half g_inT  [(size_t)NW * NB * NJ];   // [w][b][pj]  16.8 MB fp16
__device__ __half g_dropT[(size_t)NW * NI * NJ];   // [w][i][pj]  33.5 MB fp16
__device__ __half g_outTh[(size_t)NW * NB * NI];   // [w][b][i]   16.8 MB fp16

// permute j within its 16-block: pairs stay adjacent, k and k+8 pair up.
__device__ __forceinline__ int permj(int j) {
    return (j & ~15) | (((j >> 1) & 3) << 2) | (((j >> 3) & 1) << 1) | (j & 1);
}

// ---------------------------------------------------------------------------
// Kernel 1 (merged): blocks [0,1024) = dropT, blocks [1024,5120) = tin.
//   dropT[w][i][permj(j)], fp16, MUFU cos.  denom2 = 1 - 2 at cos + at^2.
//   Kerr term (~2.7e-19 rad) below fp32 eps.  (validated R6/R14)
//   tin: transpose in[b][j][w] -> inT[w][b][permj(j)], fp16.  (validated R15)
// ---------------------------------------------------------------------------
__global__ void __launch_bounds__(256) prep_kernel(
        const float* __restrict__ in,
        const float* __restrict__ phase_shift,
        const float* __restrict__ coupling) {
    __shared__ float s[32][65];
    const int t = threadIdx.x;

    if (blockIdx.x < 1024) {
        // ---- dropT part ----
        const int blk = blockIdx.x;
        const int j = (blk & 1) * 256 + t;
        const int i = blk >> 1;
        const int k = i * NJ + j;

        const double WLMIN = 1.53e-06, WLMAX = 1.57e-06;
        double c    = WLMIN + (WLMAX - WLMIN) * ((double)k / (double)(NI * NJ));
        double pref = (4.0 * M_PI * M_PI * 4.2 * 5e-06) / (c * c);   // 2*pi/fsr
        const float base = (float)(pref * (WLMIN - c)) + phase_shift[k];
        const float dphi = (float)(pref * ((WLMAX - WLMIN) / 63.0));

        float kap = fminf(fmaxf(coupling[k], 0.1f), 0.9f);
        float tc  = sqrtf(1.0f - kap * kap);
        const float alpha = (float)(1.0 - M_PI / 15000.0);
        float at  = alpha * tc;
        const float A2    = 1.0f + at * at;
        const float twoAt = 2.0f * at;
        const float coef  = kap * kap * alpha;

        __half* dst = g_dropT + (size_t)i * NJ + permj(j);
#pragma unroll 8
        for (int w = 0; w < NW; w++) {
            float ph = fmaf((float)w, dphi, base);
            float d  = __fdividef(coef, A2 - twoAt * __cosf(ph));
            dst[(size_t)w * NI * NJ] = __float2half_rn(d);
        }
    } else {
        // ---- tin part ----
        const int blk = blockIdx.x - 1024;
        const int b  = blk >> 4;
        const int j0 = (blk & 15) * 32;

        {   // load 32 j-rows x 64 w (256B per row)
            int r = t >> 3, wq = (t & 7) * 8;
            const float4* src = (const float4*)(in + ((size_t)b * NJ + j0 + r) * NW + wq);
            float4 v0 = src[0], v1 = src[1];
            s[r][wq + 0] = v0.x; s[r][wq + 1] = v0.y; s[r][wq + 2] = v0.z; s[r][wq + 3] = v0.w;
            s[r][wq + 4] = v1.x; s[r][wq + 5] = v1.y; s[r][wq + 6] = v1.z; s[r][wq + 7] = v1.w;
        }
        __syncthreads();
        {   // write 64 w-rows x 32 j as fp16, permuted (4B pair stores)
            int w = t >> 2, jg = (t & 3) * 8;
            __half* dst = g_inT + ((size_t)w * NB + b) * NJ + j0;
#pragma unroll
            for (int u = 0; u < 4; u++) {
                __half2 h = __floats2half2_rn(s[jg + 2 * u][w], s[jg + 2 * u + 1][w]);
                *(__half2*)&dst[permj(jg + 2 * u)] = h;
            }
        }
    }
}

// ---------------------------------------------------------------------------
// Kernel 2: mma.sync fp16 m16n8k16 GEMM per w-plane.
// R15 mainloop arithmetic; 3-stage cp.async ring, ONE sync per chunk,
// loads issued before compute. fp16 epilogue stores (half traffic).
// ---------------------------------------------------------------------------
#define TM 128
#define TN 128
#define KC 32                    // halves per chunk
#define NCH (NJ / KC)            // 16
#define RSB 96                   // smem row stride bytes (64B data + 32B pad)
#define SBYT (128 * RSB)         // 12288 bytes per operand-stage
#define SMEM_REQ (6 * SBYT)      // 73728 bytes (3 stages x {A,B})

#define CPA(s, g) asm volatile("cp.async.ca.shared.global [%0], [%1], 16;" :: "r"(s), "l"(g))

#define MMA_F16(c, a0, a1, a2, a3, b0, b1) \
    asm volatile("mma.sync.aligned.m16n8k16.row.col.f32.f16.f16.f32 " \
        "{%0,%1,%2,%3}, {%4,%5,%6,%7}, {%8,%9}, {%0,%1,%2,%3};" \
        : "+f"((c)[0]), "+f"((c)[1]), "+f"((c)[2]), "+f"((c)[3]) \
        : "r"(a0), "r"(a1), "r"(a2), "r"(a3), "r"(b0), "r"(b1))

#define LDSD(r0_, r1_, addr) \
    asm volatile("ld.shared.v2.b32 {%0,%1}, [%2];" : "=r"(r0_), "=r"(r1_) : "r"(addr))

static __device__ __forceinline__ uint32_t smem_u32(const void* p) {
    uint32_t a;
    asm("{ .reg .u64 t; cvta.to.shared.u64 t, %1; cvt.u32.u64 %0, t; }" : "=r"(a) : "l"(p));
    return a;
}

__global__ void __launch_bounds__(256, 2) gemm_kernel() {
    extern __shared__ char smem[];           // [A0|A1|A2|B0|B1|B2], 12288B each
    const uint32_t sbase = smem_u32(smem);

    const int tid = threadIdx.x;
    const int w   = blockIdx.x;
    const int b0  = blockIdx.y * TM;
    const int i0  = blockIdx.z * TN;

    // loader: 512 16B-units per operand per stage; thread does rows r0, r0+64
    const int r0 = tid >> 2, wc = tid & 3;
    const int r1 = r0 + 64;
    const __half* gA = g_inT   + ((size_t)w * NB + b0) * NJ;
    const __half* gB = g_dropT + ((size_t)w * NI + i0) * NJ;
    const uint32_t soA0 = (uint32_t)(r0 * RSB + wc * 16);
    const uint32_t soA1 = (uint32_t)(r1 * RSB + wc * 16);

#define STAGE(slot, jc) do { \
    CPA(sbase + (slot) * SBYT + soA0,       (const char*)(gA + (size_t)r0 * NJ + (jc)) + wc * 16); \
    CPA(sbase + (slot) * SBYT + soA1,       (const char*)(gA + (size_t)r1 * NJ + (jc)) + wc * 16); \
    CPA(sbase + (3 + (slot)) * SBYT + soA0, (const char*)(gB + (size_t)r0 * NJ + (jc)) + wc * 16); \
    CPA(sbase + (3 + (slot)) * SBYT + soA1, (const char*)(gB + (size_t)r1 * NJ + (jc)) + wc * 16); \
    asm volatile("cp.async.commit_group;" ::: "memory"); \
} while (0)

    // prologue: chunks 0,1 -> slots 0,1
    STAGE(0, 0);
    STAGE(1, KC);

    const int lane = tid & 31, wid = tid >> 5;
    const int g = lane >> 2, q = lane & 3;
    const int wm = (wid >> 2) * 64;      // warp m-offset (0/64)
    const int wn = (wid & 3) * 32;       // warp n-offset (0..96)

    float acc[4][4][4];
#pragma unroll
    for (int mt = 0; mt < 4; mt++)
#pragma unroll
        for (int nt = 0; nt < 4; nt++)
#pragma unroll
            for (int r = 0; r < 4; r++) acc[mt][nt][r] = 0.0f;

    for (int ch = 0; ch < NCH; ch++) {
        if (ch < NCH - 1) asm volatile("cp.async.wait_group 1;" ::: "memory");
        else              asm volatile("cp.async.wait_group 0;" ::: "memory");
        __syncthreads();
        // slot (ch+2)%3 == (ch-1)%3: its readers all passed the barrier above.
        if (ch + 2 < NCH) STAGE((ch + 2) % 3, (size_t)(ch + 2) * KC);

        const int slot = ch % 3;
        const uint32_t pA = sbase + slot * SBYT;
        const uint32_t pB = sbase + (3 + slot) * SBYT;

#pragma unroll
        for (int ks = 0; ks < 2; ks++) {          // 2 x k=16 per chunk
            const uint32_t k0 = (uint32_t)ks * 32 + (uint32_t)q * 8;  // bytes
            uint32_t a[4][4], b[4][2];
#pragma unroll
            for (int mt = 0; mt < 4; mt++) {
                const uint32_t ra = pA + (uint32_t)((wm + mt * 16 + g) * RSB) + k0;
                LDSD(a[mt][0], a[mt][2], ra);            // rows g:   k 2q,2q+1 | 2q+8,2q+9
                LDSD(a[mt][1], a[mt][3], ra + 8 * RSB);  // rows g+8
            }
#pragma unroll
            for (int nt = 0; nt < 4; nt++) {
                const uint32_t rb = pB + (uint32_t)((wn + nt * 8 + g) * RSB) + k0;
                LDSD(b[nt][0], b[nt][1], rb);
            }
#pragma unroll
            for (int mt = 0; mt < 4; mt++)
#pragma unroll
                for (int nt = 0; nt < 4; nt++)
                    MMA_F16(acc[mt][nt], a[mt][0], a[mt][1], a[mt][2], a[mt][3],
                            b[nt][0], b[nt][1]);
        }
    }

    // ---- epilogue: fp16 half2 stores to g_outTh[w][b][i] ----
#pragma unroll
    for (int mt = 0; mt < 4; mt++) {
        const int row = b0 + wm + mt * 16 + g;
#pragma unroll
        for (int nt = 0; nt < 4; nt++) {
            const int col = i0 + wn + nt * 8 + 2 * q;
            __half2 v0 = __floats2half2_rn(acc[mt][nt][0], acc[mt][nt][1]);
            __half2 v1 = __floats2half2_rn(acc[mt][nt][2], acc[mt][nt][3]);
            *(__half2*)&g_outTh[((size_t)w * NB + row)     * NI + col] = v0;
            *(__half2*)&g_outTh[((size_t)w * NB + row + 8) * NI + col] = v1;
        }
    }
}

// ---------------------------------------------------------------------------
// Kernel 3: transpose outTh[w][b][i] (fp16) -> out[b][i][w] (f32)
// ---------------------------------------------------------------------------
__global__ void __launch_bounds__(256) tout_kernel(float* __restrict__ out) {
    __shared__ float s[32][65];
    const int b  = blockIdx.y;
    const int i0 = blockIdx.x * 32;
    const int t  = threadIdx.x;

    {   // load 64 w-rows x 32 i (fp16, 16B per thread)
        int w = t >> 2, ig = (t & 3) * 8;
        uint4 raw = *(const uint4*)&g_outTh[((size_t)w * NB + b) * NI + i0 + ig];
        const __half2* hp = (const __half2*)&raw;
#pragma unroll
        for (int u = 0; u < 4; u++) {
            float2 f = __half22float2(hp[u]);
            s[ig + 2 * u][w]     = f.x;
            s[ig + 2 * u + 1][w] = f.y;
        }
    }
    __syncthreads();
    {   // write 32 i-rows x 64 w (256B per row)
        int r = t >> 3, wq = (t & 7) * 8;
        float* dst = out + ((size_t)b * NI + i0 + r) * NW + wq;
        float4 o0, o1;
        o0.x = s[r][wq + 0]; o0.y = s[r][wq + 1]; o0.z = s[r][wq + 2]; o0.w = s[r][wq + 3];
        o1.x = s[r][wq + 4]; o1.y = s[r][wq + 5]; o1.z = s[r][wq + 6]; o1.w = s[r][wq + 7];
        ((float4*)dst)[0] = o0; ((float4*)dst)[1] = o1;
    }
}

// ---------------------------------------------------------------------------
extern "C" void kernel_launch(void* const* d_in, const int* in_sizes, int n_in,
                              void* d_out, int out_size) {
    const float* input    = (const float*)d_in[0];  // [256,512,64]
    const float* phase    = (const float*)d_in[1];  // [512,512]
    const float* coupling = (const float*)d_in[2];  // [512,512]
    float* out            = (float*)d_out;          // [256,512,64]

    cudaFuncSetAttribute(gemm_kernel, cudaFuncAttributeMaxDynamicSharedMemorySize, SMEM_REQ);

    prep_kernel<<<5120, 256>>>(input, phase, coupling);
    gemm_kernel<<<dim3(NW, NB / TM, NI / TN), 256, SMEM_REQ>>>();
    tout_kernel<<<dim3(NI / 32, NB), 256>>>(out);
}